// round 1
// baseline (speedup 1.0000x reference)
#include <cuda_runtime.h>

// Shapes (compile-time constants)
#define BB 8
#define SS 1024
#define DD 512
#define HH 8
#define HD 64
#define DFF 2048
#define MTOK (BB*SS)   // 8192

typedef long long ll;

// ---------------- scratch (device globals: allocation-guard safe) -----------
__device__ float g_h  [MTOK*DD];        // rmsnorm1 output
__device__ float g_q  [MTOK*DD];
__device__ float g_k  [MTOK*DD];
__device__ float g_v  [MTOK*DD];
__device__ float g_sc [(ll)BB*HH*SS*SS];// attention scores / probs (268MB)
__device__ float g_ctx[MTOK*DD];
__device__ float g_y  [MTOK*DD];        // residual after attention
__device__ float g_h2 [MTOK*DD];        // rmsnorm2 output
__device__ float g_ff [MTOK*DFF];       // relu(ffn1)

// ---------------- RMSNorm: one block (128 thr) per row of 512 ---------------
__global__ __launch_bounds__(128) void rmsnorm_kernel(
    const float* __restrict__ x, const float* __restrict__ w,
    float* __restrict__ out)
{
    const int row = blockIdx.x;
    const int t = threadIdx.x; // 0..127, 4 floats each
    const float4 v = ((const float4*)(x + (ll)row*DD))[t];
    float ss = v.x*v.x + v.y*v.y + v.z*v.z + v.w*v.w;
    #pragma unroll
    for (int o = 16; o; o >>= 1) ss += __shfl_xor_sync(0xFFFFFFFFu, ss, o);
    __shared__ float wsum[4];
    if ((t & 31) == 0) wsum[t >> 5] = ss;
    __syncthreads();
    const float tot = wsum[0] + wsum[1] + wsum[2] + wsum[3];
    const float r = rsqrtf(tot * (1.0f/DD) + 1e-6f);
    const float4 wv = ((const float4*)w)[t];
    float4 o4;
    o4.x = v.x * r * wv.x; o4.y = v.y * r * wv.y;
    o4.z = v.z * r * wv.z; o4.w = v.w * r * wv.w;
    ((float4*)(out + (ll)row*DD))[t] = o4;
}

// ---------------- Generic NT SGEMM: C[m,n] = sum_k A[m,k]*B[n,k] ------------
// 128x128 tile, BK=8, 256 threads, 8x8 per-thread. All dims divisible.
// EPI: 0 = none, 1 = relu, 2 = add Add[] (same layout as C, own ld/strides)
// Batch offsets: base += (z/Hdiv)*s?1 + (z%Hdiv)*s?2
template<int EPI>
__global__ __launch_bounds__(256) void gemm_nt(
    const float* __restrict__ A, const float* __restrict__ B,
    const float* __restrict__ Add, float* __restrict__ C,
    int M, int N, int K,
    int lda, int ldb, int ldadd, int ldc,
    int Hdiv,
    ll sA1, ll sA2, ll sB1, ll sB2, ll sAdd1, ll sAdd2, ll sC1, ll sC2)
{
    const int z  = blockIdx.z;
    const int zb = z / Hdiv, zh = z % Hdiv;
    A += zb*sA1 + zh*sA2;
    B += zb*sB1 + zh*sB2;
    C += zb*sC1 + zh*sC2;
    if (EPI == 2) Add += zb*sAdd1 + zh*sAdd2;

    __shared__ float Asm[8][128];
    __shared__ float Bsm[8][128];

    const int tid  = threadIdx.x;
    const int m0   = blockIdx.y * 128;
    const int n0   = blockIdx.x * 128;
    const int arow = tid >> 1;          // 0..127
    const int acol = (tid & 1) << 2;    // 0 or 4
    const int tx   = tid & 15;
    const int ty   = tid >> 4;

    float acc[8][8];
    #pragma unroll
    for (int i = 0; i < 8; ++i)
        #pragma unroll
        for (int j = 0; j < 8; ++j) acc[i][j] = 0.f;

    for (int k0 = 0; k0 < K; k0 += 8) {
        const float4 av = *(const float4*)(A + (ll)(m0 + arow)*lda + k0 + acol);
        const float4 bv = *(const float4*)(B + (ll)(n0 + arow)*ldb + k0 + acol);
        Asm[acol+0][arow] = av.x; Asm[acol+1][arow] = av.y;
        Asm[acol+2][arow] = av.z; Asm[acol+3][arow] = av.w;
        Bsm[acol+0][arow] = bv.x; Bsm[acol+1][arow] = bv.y;
        Bsm[acol+2][arow] = bv.z; Bsm[acol+3][arow] = bv.w;
        __syncthreads();
        #pragma unroll
        for (int k = 0; k < 8; ++k) {
            float a[8], b[8];
            *(float4*)&a[0] = *(const float4*)&Asm[k][ty*8];
            *(float4*)&a[4] = *(const float4*)&Asm[k][ty*8+4];
            *(float4*)&b[0] = *(const float4*)&Bsm[k][tx*8];
            *(float4*)&b[4] = *(const float4*)&Bsm[k][tx*8+4];
            #pragma unroll
            for (int i = 0; i < 8; ++i)
                #pragma unroll
                for (int j = 0; j < 8; ++j)
                    acc[i][j] += a[i]*b[j];
        }
        __syncthreads();
    }

    #pragma unroll
    for (int i = 0; i < 8; ++i) {
        const ll crow = (ll)(m0 + ty*8 + i);
        float* cp = C + crow*ldc + n0 + tx*8;
        #pragma unroll
        for (int jj = 0; jj < 8; jj += 4) {
            float4 v;
            v.x = acc[i][jj+0]; v.y = acc[i][jj+1];
            v.z = acc[i][jj+2]; v.w = acc[i][jj+3];
            if (EPI == 1) {
                v.x = fmaxf(v.x, 0.f); v.y = fmaxf(v.y, 0.f);
                v.z = fmaxf(v.z, 0.f); v.w = fmaxf(v.w, 0.f);
            }
            if (EPI == 2) {
                const float4 ad = *(const float4*)(Add + crow*ldadd + n0 + tx*8 + jj);
                v.x += ad.x; v.y += ad.y; v.z += ad.z; v.w += ad.w;
            }
            *(float4*)(cp + jj) = v;
        }
    }
}

// ---------------- Softmax over last dim (1024), in place --------------------
__global__ __launch_bounds__(256) void softmax_kernel(float* __restrict__ S)
{
    const ll row = blockIdx.x;
    float4* p = (float4*)(S + row * (ll)SS);
    const int t = threadIdx.x; // 256 threads * 4 = 1024
    float4 v = p[t];
    float m = fmaxf(fmaxf(v.x, v.y), fmaxf(v.z, v.w));
    #pragma unroll
    for (int o = 16; o; o >>= 1) m = fmaxf(m, __shfl_xor_sync(0xFFFFFFFFu, m, o));
    __shared__ float shm[8];
    __shared__ float shs[8];
    if ((t & 31) == 0) shm[t >> 5] = m;
    __syncthreads();
    float bm = shm[0];
    #pragma unroll
    for (int i = 1; i < 8; ++i) bm = fmaxf(bm, shm[i]);
    v.x = __expf(v.x - bm); v.y = __expf(v.y - bm);
    v.z = __expf(v.z - bm); v.w = __expf(v.w - bm);
    float s = v.x + v.y + v.z + v.w;
    #pragma unroll
    for (int o = 16; o; o >>= 1) s += __shfl_xor_sync(0xFFFFFFFFu, s, o);
    if ((t & 31) == 0) shs[t >> 5] = s;
    __syncthreads();
    float tot = shs[0];
    #pragma unroll
    for (int i = 1; i < 8; ++i) tot += shs[i];
    const float inv = 1.0f / tot;
    v.x *= inv; v.y *= inv; v.z *= inv; v.w *= inv;
    p[t] = v;
}

// ---------------- P @ V (NN), per-(b,h), writes ctx in [B,S,D] layout -------
// 64x64 tile, BK=16, 256 threads, 4x4 per-thread. N = HD = 64 (one tile).
__global__ __launch_bounds__(256) void attn_pv(
    const float* __restrict__ P, const float* __restrict__ V,
    float* __restrict__ Cx)
{
    const int z  = blockIdx.y;                 // b*H + h
    const int m0 = blockIdx.x * 64;
    const float* Pz = P + (ll)z * SS * SS;
    const ll qkv_off = (ll)(z >> 3) * SS * DD + (ll)(z & 7) * HD;
    const float* Vz = V  + qkv_off;
    float*       Cz = Cx + qkv_off;

    __shared__ float Asm[16][64];
    __shared__ float Bsm[16][64];

    const int tid  = threadIdx.x;
    const int arow = tid >> 2;         // 0..63
    const int acol = (tid & 3) << 2;   // 0,4,8,12
    const int brow = tid >> 4;         // 0..15
    const int bcol = (tid & 15) << 2;  // 0..60
    const int ty = tid >> 4;           // 0..15
    const int tx = tid & 15;           // 0..15

    float acc[4][4];
    #pragma unroll
    for (int i = 0; i < 4; ++i)
        #pragma unroll
        for (int j = 0; j < 4; ++j) acc[i][j] = 0.f;

    for (int k0 = 0; k0 < SS; k0 += 16) {
        const float4 av = *(const float4*)(Pz + (ll)(m0 + arow)*SS + k0 + acol);
        Asm[acol+0][arow] = av.x; Asm[acol+1][arow] = av.y;
        Asm[acol+2][arow] = av.z; Asm[acol+3][arow] = av.w;
        const float4 bv = *(const float4*)(Vz + (ll)(k0 + brow)*DD + bcol);
        *(float4*)&Bsm[brow][bcol] = bv;
        __syncthreads();
        #pragma unroll
        for (int k = 0; k < 16; ++k) {
            float a[4], b[4];
            *(float4*)a = *(const float4*)&Asm[k][ty*4];
            *(float4*)b = *(const float4*)&Bsm[k][tx*4];
            #pragma unroll
            for (int i = 0; i < 4; ++i)
                #pragma unroll
                for (int j = 0; j < 4; ++j)
                    acc[i][j] += a[i]*b[j];
        }
        __syncthreads();
    }

    #pragma unroll
    for (int i = 0; i < 4; ++i) {
        float4 v;
        v.x = acc[i][0]; v.y = acc[i][1]; v.z = acc[i][2]; v.w = acc[i][3];
        *(float4*)(Cz + (ll)(m0 + ty*4 + i)*DD + tx*4) = v;
    }
}

// ---------------- host orchestration ----------------------------------------
extern "C" void kernel_launch(void* const* d_in, const int* in_sizes, int n_in,
                              void* d_out, int out_size)
{
    const float* Wk   = (const float*)d_in[0]; // primals_1
    const float* Wo   = (const float*)d_in[1]; // primals_2
    const float* Wq   = (const float*)d_in[2]; // primals_3
    const float* Wv   = (const float*)d_in[3]; // primals_4
    const float* G1   = (const float*)d_in[4]; // primals_5
    const float* Wi   = (const float*)d_in[5]; // primals_6 [DFF,D]
    const float* Wo2  = (const float*)d_in[6]; // primals_7 [D,DFF]
    const float* G2   = (const float*)d_in[7]; // primals_8
    const float* X    = (const float*)d_in[8]; // primals_9 [B,S,D]
    const float* Bias = (const float*)d_in[9]; // primals_10 [B,H,S,S]
    float* Out = (float*)d_out;

    float *h, *q, *k, *v, *sc, *ctx, *y, *h2, *ff;
    cudaGetSymbolAddress((void**)&h,   g_h);
    cudaGetSymbolAddress((void**)&q,   g_q);
    cudaGetSymbolAddress((void**)&k,   g_k);
    cudaGetSymbolAddress((void**)&v,   g_v);
    cudaGetSymbolAddress((void**)&sc,  g_sc);
    cudaGetSymbolAddress((void**)&ctx, g_ctx);
    cudaGetSymbolAddress((void**)&y,   g_y);
    cudaGetSymbolAddress((void**)&h2,  g_h2);
    cudaGetSymbolAddress((void**)&ff,  g_ff);

    const dim3 blk(256);

    // 1) h = rmsnorm(x, G1)
    rmsnorm_kernel<<<MTOK, 128>>>(X, G1, h);

    // 2) q/k/v = h @ W^T  (NT, M=8192 N=512 K=512)
    gemm_nt<0><<<dim3(4,64,1), blk>>>(h, Wq, nullptr, q, MTOK, DD, DD,
        DD, DD, 0, DD, 1, 0,0, 0,0, 0,0, 0,0);
    gemm_nt<0><<<dim3(4,64,1), blk>>>(h, Wk, nullptr, k, MTOK, DD, DD,
        DD, DD, 0, DD, 1, 0,0, 0,0, 0,0, 0,0);
    gemm_nt<0><<<dim3(4,64,1), blk>>>(h, Wv, nullptr, v, MTOK, DD, DD,
        DD, DD, 0, DD, 1, 0,0, 0,0, 0,0, 0,0);

    // 3) scores = q @ k^T + bias  (batched over 64 (b,h), M=N=1024, K=64)
    gemm_nt<2><<<dim3(8,8,BB*HH), blk>>>(q, k, Bias, sc, SS, SS, HD,
        DD, DD, SS, SS, HH,
        (ll)SS*DD, (ll)HD,           // A (g_q): b-stride, h-stride
        (ll)SS*DD, (ll)HD,           // B (g_k)
        (ll)HH*SS*SS, (ll)SS*SS,     // Add (bias)
        (ll)HH*SS*SS, (ll)SS*SS);    // C (scores)

    // 4) softmax rows
    softmax_kernel<<<BB*HH*SS, 256>>>(sc);

    // 5) ctx = P @ V, written directly in [B,S,D] layout
    attn_pv<<<dim3(SS/64, BB*HH), blk>>>(sc, v, ctx);

    // 6) y = x + ctx @ Wo^T
    gemm_nt<2><<<dim3(4,64,1), blk>>>(ctx, Wo, X, y, MTOK, DD, DD,
        DD, DD, DD, DD, 1, 0,0, 0,0, 0,0, 0,0);

    // 7) h2 = rmsnorm(y, G2)
    rmsnorm_kernel<<<MTOK, 128>>>(y, G2, h2);

    // 8) ff = relu(h2 @ Wi^T)   (M=8192 N=2048 K=512)
    gemm_nt<1><<<dim3(16,64,1), blk>>>(h2, Wi, nullptr, ff, MTOK, DFF, DD,
        DD, DD, 0, DFF, 1, 0,0, 0,0, 0,0, 0,0);

    // 9) out = y + ff @ Wo2^T   (M=8192 N=512 K=2048)
    gemm_nt<2><<<dim3(4,64,1), blk>>>(ff, Wo2, y, Out, MTOK, DD, DFF,
        DFF, DFF, DD, DD, 1, 0,0, 0,0, 0,0, 0,0);
}

// round 2
// speedup vs baseline: 2.1631x; 2.1631x over previous
#include <cuda_runtime.h>
#include <cstdint>

// Shapes (compile-time constants)
#define BB 8
#define SS 1024
#define DD 512
#define HH 8
#define HD 64
#define DFF 2048
#define MTOK (BB*SS)   // 8192

typedef long long ll;

// ---------------- scratch (device globals: allocation-guard safe) -----------
__device__ float g_h  [MTOK*DD];        // rmsnorm1 output
__device__ float g_q  [MTOK*DD];
__device__ float g_k  [MTOK*DD];
__device__ float g_v  [MTOK*DD];
__device__ float g_sc [(ll)BB*HH*SS*SS];// attention scores / probs (268MB)
__device__ float g_ctx[MTOK*DD];
__device__ float g_y  [MTOK*DD];        // residual after attention
__device__ float g_h2 [MTOK*DD];        // rmsnorm2 output
__device__ float g_ff [MTOK*DFF];       // relu(ffn1)

// ---------------- helpers ---------------------------------------------------
__device__ __forceinline__ float ftf32(float x) {
    uint32_t o, i = __float_as_uint(x);
    asm("cvt.rna.tf32.f32 %0, %1;" : "=r"(o) : "r"(i));
    return __uint_as_float(o);
}

__device__ __forceinline__ void mma_tf32(float c[4], const uint32_t a[4], const uint32_t b[2]) {
    asm volatile(
        "mma.sync.aligned.m16n8k8.row.col.f32.tf32.tf32.f32 "
        "{%0,%1,%2,%3}, {%4,%5,%6,%7}, {%8,%9}, {%0,%1,%2,%3};\n"
        : "+f"(c[0]), "+f"(c[1]), "+f"(c[2]), "+f"(c[3])
        : "r"(a[0]), "r"(a[1]), "r"(a[2]), "r"(a[3]), "r"(b[0]), "r"(b[1]));
}

// ---------------- RMSNorm: one block (128 thr) per row of 512 ---------------
__global__ __launch_bounds__(128) void rmsnorm_kernel(
    const float* __restrict__ x, const float* __restrict__ w,
    float* __restrict__ out)
{
    const int row = blockIdx.x;
    const int t = threadIdx.x;
    const float4 v = ((const float4*)(x + (ll)row*DD))[t];
    float ss = v.x*v.x + v.y*v.y + v.z*v.z + v.w*v.w;
    #pragma unroll
    for (int o = 16; o; o >>= 1) ss += __shfl_xor_sync(0xFFFFFFFFu, ss, o);
    __shared__ float wsum[4];
    if ((t & 31) == 0) wsum[t >> 5] = ss;
    __syncthreads();
    const float tot = wsum[0] + wsum[1] + wsum[2] + wsum[3];
    const float r = rsqrtf(tot * (1.0f/DD) + 1e-6f);
    const float4 wv = ((const float4*)w)[t];
    float4 o4;
    o4.x = v.x * r * wv.x; o4.y = v.y * r * wv.y;
    o4.z = v.z * r * wv.z; o4.w = v.w * r * wv.w;
    ((float4*)(out + (ll)row*DD))[t] = o4;
}

// ---------------- TF32 tensor-core GEMM -------------------------------------
// C[m,n] = sum_k A[m,k] * B'[n,k]   (A row-major k-contig)
// BT=true : B given as [n][k] k-contig (NT case)
// BT=false: B given as [k][n] n-contig (NN case; transposed while staging)
// EPI: 0=none, 1=relu, 2=+Add
// Block tile BM=128 x BN x BK=16, 256 threads (8 warps, 4x2),
// warp tile 32 x (BN/2), mma m16n8k8, tf32 rounding at smem-store time.
template<int EPI, int BN, bool BT>
__global__ __launch_bounds__(256) void gemm_tc(
    const float* __restrict__ A, const float* __restrict__ B,
    const float* __restrict__ Add, float* __restrict__ C,
    int M, int N, int K,
    int lda, int ldb, int ldadd, int ldc,
    int Hdiv,
    ll sA1, ll sA2, ll sB1, ll sB2, ll sAdd1, ll sAdd2, ll sC1, ll sC2)
{
    constexpr int BM = 128, BK = 16, LDS = BK + 4; // pad: conflict-free frag reads
    constexpr int A_F4 = BM*BK/(4*256);            // 2
    constexpr int B_F4 = BN*BK/(4*256);            // 2 (BN=128) / 1 (BN=64)
    constexpr int WN = BN/2;
    constexpr int NT = WN/8;                       // 8 or 4

    const int z  = blockIdx.z;
    const int zb = z / Hdiv, zh = z % Hdiv;
    A += zb*sA1 + zh*sA2;
    B += zb*sB1 + zh*sB2;
    C += zb*sC1 + zh*sC2;
    if (EPI == 2) Add += zb*sAdd1 + zh*sAdd2;

    __shared__ float Asm[2][BM][LDS];
    __shared__ float Bsm[2][BN][LDS];

    const int tid  = threadIdx.x;
    const int m0   = blockIdx.y * BM;
    const int n0   = blockIdx.x * BN;
    const int warp = tid >> 5, lane = tid & 31;
    const int wm   = warp & 3, wn = warp >> 2;
    const int gid  = lane >> 2, tig = lane & 3;

    float acc[2][NT][4];
    #pragma unroll
    for (int mt = 0; mt < 2; ++mt)
        #pragma unroll
        for (int nt = 0; nt < NT; ++nt)
            #pragma unroll
            for (int i = 0; i < 4; ++i) acc[mt][nt][i] = 0.f;

    float4 pa[A_F4], pb[B_F4];
    const int ntile = K / BK;

    // ---- global -> regs for tile kt
    auto loadg = [&](int kt) {
        const int k0 = kt * BK;
        #pragma unroll
        for (int i = 0; i < A_F4; ++i) {
            const int idx = tid + i*256;
            const int r = idx >> 2, c = (idx & 3) << 2;
            pa[i] = *(const float4*)(A + (ll)(m0 + r)*lda + k0 + c);
        }
        #pragma unroll
        for (int i = 0; i < B_F4; ++i) {
            const int idx = tid + i*256;
            if (BT) {
                const int r = idx >> 2, c = (idx & 3) << 2;
                pb[i] = *(const float4*)(B + (ll)(n0 + r)*ldb + k0 + c);
            } else {
                const int kk = idx / (BN/4), nn = (idx % (BN/4)) << 2;
                pb[i] = *(const float4*)(B + (ll)(k0 + kk)*ldb + n0 + nn);
            }
        }
    };
    // ---- regs -> smem (with tf32 rounding)
    auto stores = [&](int buf) {
        #pragma unroll
        for (int i = 0; i < A_F4; ++i) {
            const int idx = tid + i*256;
            const int r = idx >> 2, c = (idx & 3) << 2;
            float4 v = pa[i];
            v.x = ftf32(v.x); v.y = ftf32(v.y); v.z = ftf32(v.z); v.w = ftf32(v.w);
            *(float4*)&Asm[buf][r][c] = v;
        }
        #pragma unroll
        for (int i = 0; i < B_F4; ++i) {
            const int idx = tid + i*256;
            float4 v = pb[i];
            v.x = ftf32(v.x); v.y = ftf32(v.y); v.z = ftf32(v.z); v.w = ftf32(v.w);
            if (BT) {
                const int r = idx >> 2, c = (idx & 3) << 2;
                *(float4*)&Bsm[buf][r][c] = v;
            } else {
                const int kk = idx / (BN/4), nn = (idx % (BN/4)) << 2;
                Bsm[buf][nn+0][kk] = v.x; Bsm[buf][nn+1][kk] = v.y;
                Bsm[buf][nn+2][kk] = v.z; Bsm[buf][nn+3][kk] = v.w;
            }
        }
    };

    loadg(0);
    stores(0);
    __syncthreads();

    int buf = 0;
    for (int kt = 0; kt < ntile; ++kt) {
        if (kt + 1 < ntile) loadg(kt + 1);

        #pragma unroll
        for (int ks = 0; ks < 2; ++ks) {
            const int k = ks*8 + tig;
            uint32_t af[2][4], bf[NT][2];
            #pragma unroll
            for (int mt = 0; mt < 2; ++mt) {
                const int r = wm*32 + mt*16 + gid;
                af[mt][0] = __float_as_uint(Asm[buf][r  ][k  ]);
                af[mt][1] = __float_as_uint(Asm[buf][r+8][k  ]);
                af[mt][2] = __float_as_uint(Asm[buf][r  ][k+4]);
                af[mt][3] = __float_as_uint(Asm[buf][r+8][k+4]);
            }
            #pragma unroll
            for (int nt = 0; nt < NT; ++nt) {
                const int cc = wn*WN + nt*8 + gid;
                bf[nt][0] = __float_as_uint(Bsm[buf][cc][k  ]);
                bf[nt][1] = __float_as_uint(Bsm[buf][cc][k+4]);
            }
            #pragma unroll
            for (int mt = 0; mt < 2; ++mt)
                #pragma unroll
                for (int nt = 0; nt < NT; ++nt)
                    mma_tf32(acc[mt][nt], af[mt], bf[nt]);
        }

        if (kt + 1 < ntile) stores(buf ^ 1);
        __syncthreads();
        buf ^= 1;
    }

    // ---- epilogue
    #pragma unroll
    for (int mt = 0; mt < 2; ++mt) {
        #pragma unroll
        for (int nt = 0; nt < NT; ++nt) {
            const int col = n0 + wn*WN + nt*8 + tig*2;
            #pragma unroll
            for (int h = 0; h < 2; ++h) {
                const ll row = (ll)(m0 + wm*32 + mt*16 + gid + h*8);
                float2 v;
                v.x = acc[mt][nt][h*2+0];
                v.y = acc[mt][nt][h*2+1];
                if (EPI == 1) { v.x = fmaxf(v.x, 0.f); v.y = fmaxf(v.y, 0.f); }
                if (EPI == 2) {
                    const float2 ad = *(const float2*)(Add + row*ldadd + col);
                    v.x += ad.x; v.y += ad.y;
                }
                *(float2*)(C + row*ldc + col) = v;
            }
        }
    }
}

// ---------------- Softmax over last dim (1024), in place --------------------
__global__ __launch_bounds__(256) void softmax_kernel(float* __restrict__ S)
{
    const ll row = blockIdx.x;
    float4* p = (float4*)(S + row * (ll)SS);
    const int t = threadIdx.x;
    float4 v = p[t];
    float m = fmaxf(fmaxf(v.x, v.y), fmaxf(v.z, v.w));
    #pragma unroll
    for (int o = 16; o; o >>= 1) m = fmaxf(m, __shfl_xor_sync(0xFFFFFFFFu, m, o));
    __shared__ float shm[8];
    __shared__ float shs[8];
    if ((t & 31) == 0) shm[t >> 5] = m;
    __syncthreads();
    float bm = shm[0];
    #pragma unroll
    for (int i = 1; i < 8; ++i) bm = fmaxf(bm, shm[i]);
    v.x = __expf(v.x - bm); v.y = __expf(v.y - bm);
    v.z = __expf(v.z - bm); v.w = __expf(v.w - bm);
    float s = v.x + v.y + v.z + v.w;
    #pragma unroll
    for (int o = 16; o; o >>= 1) s += __shfl_xor_sync(0xFFFFFFFFu, s, o);
    if ((t & 31) == 0) shs[t >> 5] = s;
    __syncthreads();
    float tot = shs[0];
    #pragma unroll
    for (int i = 1; i < 8; ++i) tot += shs[i];
    const float inv = 1.0f / tot;
    v.x *= inv; v.y *= inv; v.z *= inv; v.w *= inv;
    p[t] = v;
}

// ---------------- host orchestration ----------------------------------------
extern "C" void kernel_launch(void* const* d_in, const int* in_sizes, int n_in,
                              void* d_out, int out_size)
{
    const float* Wk   = (const float*)d_in[0]; // primals_1
    const float* Wo   = (const float*)d_in[1]; // primals_2
    const float* Wq   = (const float*)d_in[2]; // primals_3
    const float* Wv   = (const float*)d_in[3]; // primals_4
    const float* G1   = (const float*)d_in[4]; // primals_5
    const float* Wi   = (const float*)d_in[5]; // primals_6 [DFF,D]
    const float* Wo2  = (const float*)d_in[6]; // primals_7 [D,DFF]
    const float* G2   = (const float*)d_in[7]; // primals_8
    const float* X    = (const float*)d_in[8]; // primals_9 [B,S,D]
    const float* Bias = (const float*)d_in[9]; // primals_10 [B,H,S,S]
    float* Out = (float*)d_out;

    float *h, *q, *k, *v, *sc, *ctx, *y, *h2, *ff;
    cudaGetSymbolAddress((void**)&h,   g_h);
    cudaGetSymbolAddress((void**)&q,   g_q);
    cudaGetSymbolAddress((void**)&k,   g_k);
    cudaGetSymbolAddress((void**)&v,   g_v);
    cudaGetSymbolAddress((void**)&sc,  g_sc);
    cudaGetSymbolAddress((void**)&ctx, g_ctx);
    cudaGetSymbolAddress((void**)&y,   g_y);
    cudaGetSymbolAddress((void**)&h2,  g_h2);
    cudaGetSymbolAddress((void**)&ff,  g_ff);

    const dim3 blk(256);

    // 1) h = rmsnorm(x, G1)
    rmsnorm_kernel<<<MTOK, 128>>>(X, G1, h);

    // 2) q/k/v = h @ W^T  (NT, M=8192 N=512 K=512)
    gemm_tc<0,128,true><<<dim3(4,64,1), blk>>>(h, Wq, nullptr, q, MTOK, DD, DD,
        DD, DD, 0, DD, 1, 0,0, 0,0, 0,0, 0,0);
    gemm_tc<0,128,true><<<dim3(4,64,1), blk>>>(h, Wk, nullptr, k, MTOK, DD, DD,
        DD, DD, 0, DD, 1, 0,0, 0,0, 0,0, 0,0);
    gemm_tc<0,128,true><<<dim3(4,64,1), blk>>>(h, Wv, nullptr, v, MTOK, DD, DD,
        DD, DD, 0, DD, 1, 0,0, 0,0, 0,0, 0,0);

    // 3) scores = q @ k^T + bias  (batched over 64 (b,h), M=N=1024, K=64)
    gemm_tc<2,128,true><<<dim3(8,8,BB*HH), blk>>>(q, k, Bias, sc, SS, SS, HD,
        DD, DD, SS, SS, HH,
        (ll)SS*DD, (ll)HD,
        (ll)SS*DD, (ll)HD,
        (ll)HH*SS*SS, (ll)SS*SS,
        (ll)HH*SS*SS, (ll)SS*SS);

    // 4) softmax rows
    softmax_kernel<<<BB*HH*SS, 256>>>(sc);

    // 5) ctx = P @ V  (NN, per (b,h), M=1024 N=64 K=1024) -> [B,S,D] layout
    gemm_tc<0,64,false><<<dim3(1,8,BB*HH), blk>>>(sc, v, nullptr, ctx, SS, HD, SS,
        SS, DD, 0, DD, HH,
        (ll)HH*SS*SS, (ll)SS*SS,
        (ll)SS*DD, (ll)HD,
        0, 0,
        (ll)SS*DD, (ll)HD);

    // 6) y = x + ctx @ Wo^T
    gemm_tc<2,128,true><<<dim3(4,64,1), blk>>>(ctx, Wo, X, y, MTOK, DD, DD,
        DD, DD, DD, DD, 1, 0,0, 0,0, 0,0, 0,0);

    // 7) h2 = rmsnorm(y, G2)
    rmsnorm_kernel<<<MTOK, 128>>>(y, G2, h2);

    // 8) ff = relu(h2 @ Wi^T)   (M=8192 N=2048 K=512)
    gemm_tc<1,128,true><<<dim3(16,64,1), blk>>>(h2, Wi, nullptr, ff, MTOK, DFF, DD,
        DD, DD, 0, DFF, 1, 0,0, 0,0, 0,0, 0,0);

    // 9) out = y + ff @ Wo2^T   (M=8192 N=512 K=2048)
    gemm_tc<2,128,true><<<dim3(4,64,1), blk>>>(ff, Wo2, y, Out, MTOK, DD, DFF,
        DFF, DFF, DD, DD, 1, 0,0, 0,0, 0,0, 0,0);
}

// round 3
// speedup vs baseline: 2.3769x; 1.0988x over previous
#include <cuda_runtime.h>
#include <cstdint>

// Shapes (compile-time constants)
#define BB 8
#define SS 1024
#define DD 512
#define HH 8
#define HD 64
#define DFF 2048
#define MTOK (BB*SS)   // 8192

typedef long long ll;

// ---------------- scratch (device globals: allocation-guard safe) -----------
__device__ float g_h  [MTOK*DD];        // rmsnorm1 output
__device__ float g_q  [MTOK*DD];
__device__ float g_k  [MTOK*DD];
__device__ float g_v  [MTOK*DD];
__device__ float g_ctx[MTOK*DD];
__device__ float g_y  [MTOK*DD];        // residual after attention
__device__ float g_h2 [MTOK*DD];        // rmsnorm2 output
__device__ float g_ff [MTOK*DFF];       // relu(ffn1)

// ---------------- helpers ---------------------------------------------------
__device__ __forceinline__ float ftf32(float x) {
    uint32_t o, i = __float_as_uint(x);
    asm("cvt.rna.tf32.f32 %0, %1;" : "=r"(o) : "r"(i));
    return __uint_as_float(o);
}

__device__ __forceinline__ void mma_tf32(float c[4], const uint32_t a[4], const uint32_t b[2]) {
    asm volatile(
        "mma.sync.aligned.m16n8k8.row.col.f32.tf32.tf32.f32 "
        "{%0,%1,%2,%3}, {%4,%5,%6,%7}, {%8,%9}, {%0,%1,%2,%3};\n"
        : "+f"(c[0]), "+f"(c[1]), "+f"(c[2]), "+f"(c[3])
        : "r"(a[0]), "r"(a[1]), "r"(a[2]), "r"(a[3]), "r"(b[0]), "r"(b[1]));
}

// ---------------- RMSNorm: one block (128 thr) per row of 512 ---------------
__global__ __launch_bounds__(128) void rmsnorm_kernel(
    const float* __restrict__ x, const float* __restrict__ w,
    float* __restrict__ out)
{
    const int row = blockIdx.x;
    const int t = threadIdx.x;
    const float4 v = ((const float4*)(x + (ll)row*DD))[t];
    float ss = v.x*v.x + v.y*v.y + v.z*v.z + v.w*v.w;
    #pragma unroll
    for (int o = 16; o; o >>= 1) ss += __shfl_xor_sync(0xFFFFFFFFu, ss, o);
    __shared__ float wsum[4];
    if ((t & 31) == 0) wsum[t >> 5] = ss;
    __syncthreads();
    const float tot = wsum[0] + wsum[1] + wsum[2] + wsum[3];
    const float r = rsqrtf(tot * (1.0f/DD) + 1e-6f);
    const float4 wv = ((const float4*)w)[t];
    float4 o4;
    o4.x = v.x * r * wv.x; o4.y = v.y * r * wv.y;
    o4.z = v.z * r * wv.z; o4.w = v.w * r * wv.w;
    ((float4*)(out + (ll)row*DD))[t] = o4;
}

// ---------------- TF32 tensor-core GEMM (projections / FFN) -----------------
template<int EPI, int BN, bool BT>
__global__ __launch_bounds__(256) void gemm_tc(
    const float* __restrict__ A, const float* __restrict__ B,
    const float* __restrict__ Add, float* __restrict__ C,
    int M, int N, int K,
    int lda, int ldb, int ldadd, int ldc,
    int Hdiv,
    ll sA1, ll sA2, ll sB1, ll sB2, ll sAdd1, ll sAdd2, ll sC1, ll sC2)
{
    constexpr int BM = 128, BK = 16, LDS = BK + 4;
    constexpr int A_F4 = BM*BK/(4*256);
    constexpr int B_F4 = BN*BK/(4*256);
    constexpr int WN = BN/2;
    constexpr int NT = WN/8;

    const int z  = blockIdx.z;
    const int zb = z / Hdiv, zh = z % Hdiv;
    A += zb*sA1 + zh*sA2;
    B += zb*sB1 + zh*sB2;
    C += zb*sC1 + zh*sC2;
    if (EPI == 2) Add += zb*sAdd1 + zh*sAdd2;

    __shared__ float Asm[2][BM][LDS];
    __shared__ float Bsm[2][BN][LDS];

    const int tid  = threadIdx.x;
    const int m0   = blockIdx.y * BM;
    const int n0   = blockIdx.x * BN;
    const int warp = tid >> 5, lane = tid & 31;
    const int wm   = warp & 3, wn = warp >> 2;
    const int gid  = lane >> 2, tig = lane & 3;

    float acc[2][NT][4];
    #pragma unroll
    for (int mt = 0; mt < 2; ++mt)
        #pragma unroll
        for (int nt = 0; nt < NT; ++nt)
            #pragma unroll
            for (int i = 0; i < 4; ++i) acc[mt][nt][i] = 0.f;

    float4 pa[A_F4], pb[B_F4];
    const int ntile = K / BK;

    auto loadg = [&](int kt) {
        const int k0 = kt * BK;
        #pragma unroll
        for (int i = 0; i < A_F4; ++i) {
            const int idx = tid + i*256;
            const int r = idx >> 2, c = (idx & 3) << 2;
            pa[i] = *(const float4*)(A + (ll)(m0 + r)*lda + k0 + c);
        }
        #pragma unroll
        for (int i = 0; i < B_F4; ++i) {
            const int idx = tid + i*256;
            if (BT) {
                const int r = idx >> 2, c = (idx & 3) << 2;
                pb[i] = *(const float4*)(B + (ll)(n0 + r)*ldb + k0 + c);
            } else {
                const int kk = idx / (BN/4), nn = (idx % (BN/4)) << 2;
                pb[i] = *(const float4*)(B + (ll)(k0 + kk)*ldb + n0 + nn);
            }
        }
    };
    auto stores = [&](int buf) {
        #pragma unroll
        for (int i = 0; i < A_F4; ++i) {
            const int idx = tid + i*256;
            const int r = idx >> 2, c = (idx & 3) << 2;
            float4 v = pa[i];
            v.x = ftf32(v.x); v.y = ftf32(v.y); v.z = ftf32(v.z); v.w = ftf32(v.w);
            *(float4*)&Asm[buf][r][c] = v;
        }
        #pragma unroll
        for (int i = 0; i < B_F4; ++i) {
            const int idx = tid + i*256;
            float4 v = pb[i];
            v.x = ftf32(v.x); v.y = ftf32(v.y); v.z = ftf32(v.z); v.w = ftf32(v.w);
            if (BT) {
                const int r = idx >> 2, c = (idx & 3) << 2;
                *(float4*)&Bsm[buf][r][c] = v;
            } else {
                const int kk = idx / (BN/4), nn = (idx % (BN/4)) << 2;
                Bsm[buf][nn+0][kk] = v.x; Bsm[buf][nn+1][kk] = v.y;
                Bsm[buf][nn+2][kk] = v.z; Bsm[buf][nn+3][kk] = v.w;
            }
        }
    };

    loadg(0);
    stores(0);
    __syncthreads();

    int buf = 0;
    for (int kt = 0; kt < ntile; ++kt) {
        if (kt + 1 < ntile) loadg(kt + 1);

        #pragma unroll
        for (int ks = 0; ks < 2; ++ks) {
            const int k = ks*8 + tig;
            uint32_t af[2][4], bf[NT][2];
            #pragma unroll
            for (int mt = 0; mt < 2; ++mt) {
                const int r = wm*32 + mt*16 + gid;
                af[mt][0] = __float_as_uint(Asm[buf][r  ][k  ]);
                af[mt][1] = __float_as_uint(Asm[buf][r+8][k  ]);
                af[mt][2] = __float_as_uint(Asm[buf][r  ][k+4]);
                af[mt][3] = __float_as_uint(Asm[buf][r+8][k+4]);
            }
            #pragma unroll
            for (int nt = 0; nt < NT; ++nt) {
                const int cc = wn*WN + nt*8 + gid;
                bf[nt][0] = __float_as_uint(Bsm[buf][cc][k  ]);
                bf[nt][1] = __float_as_uint(Bsm[buf][cc][k+4]);
            }
            #pragma unroll
            for (int mt = 0; mt < 2; ++mt)
                #pragma unroll
                for (int nt = 0; nt < NT; ++nt)
                    mma_tf32(acc[mt][nt], af[mt], bf[nt]);
        }

        if (kt + 1 < ntile) stores(buf ^ 1);
        __syncthreads();
        buf ^= 1;
    }

    #pragma unroll
    for (int mt = 0; mt < 2; ++mt) {
        #pragma unroll
        for (int nt = 0; nt < NT; ++nt) {
            const int col = n0 + wn*WN + nt*8 + tig*2;
            #pragma unroll
            for (int h = 0; h < 2; ++h) {
                const ll row = (ll)(m0 + wm*32 + mt*16 + gid + h*8);
                float2 v;
                v.x = acc[mt][nt][h*2+0];
                v.y = acc[mt][nt][h*2+1];
                if (EPI == 1) { v.x = fmaxf(v.x, 0.f); v.y = fmaxf(v.y, 0.f); }
                if (EPI == 2) {
                    const float2 ad = *(const float2*)(Add + row*ldadd + col);
                    v.x += ad.x; v.y += ad.y;
                }
                *(float2*)(C + row*ldc + col) = v;
            }
        }
    }
}

// ---------------- Fused flash attention -------------------------------------
// One block = 128 q-rows of one (b,h). 256 threads, 8 warps; warp owns 16 rows.
// Streams K/V in 64-key tiles. Bias added from gmem (read once).
// Online softmax; O accumulated fp32 in registers; ctx written in [B,S,D].
#define FQ 128
#define FK 64
#define FLDS 68   // 64 + 4 pad

struct FlashS {
    float stage[FQ][FLDS];  // Q (prologue) then P (per-iter, warp-local)
    float ks[FK][FLDS];     // K tile [key][d]
    float vs[HD][FLDS];     // V tile transposed [d][key]
};

__global__ __launch_bounds__(256) void flash_attn(
    const float* __restrict__ Q, const float* __restrict__ Kg,
    const float* __restrict__ Vg, const float* __restrict__ Bias,
    float* __restrict__ Ctx)
{
    extern __shared__ char smraw[];
    FlashS& sm = *reinterpret_cast<FlashS*>(smraw);

    const int z  = blockIdx.y;          // b*H + h
    const int b  = z >> 3, hh = z & 7;
    const int q0 = blockIdx.x * FQ;
    const ll off = (ll)b*SS*DD + (ll)hh*HD;
    const float* Qz = Q  + off;
    const float* Kz = Kg + off;
    const float* Vz = Vg + off;
    const float* Bz = Bias + ((ll)z*SS + q0)*SS;
    float*       Cz = Ctx + off;

    const int tid = threadIdx.x, warp = tid >> 5, lane = tid & 31;
    const int gid = lane >> 2, tig = lane & 3;
    const int wrow = warp * 16;

    // ---- prologue: Q tile -> smem (tf32) -> register A-fragments
    #pragma unroll
    for (int i = 0; i < 8; ++i) {
        const int idx = tid + i*256;
        const int r = idx >> 4, c = (idx & 15) << 2;
        float4 v = *(const float4*)(Qz + (ll)(q0 + r)*DD + c);
        v.x = ftf32(v.x); v.y = ftf32(v.y); v.z = ftf32(v.z); v.w = ftf32(v.w);
        *(float4*)&sm.stage[r][c] = v;
    }
    __syncthreads();
    uint32_t qf[8][4];
    #pragma unroll
    for (int kc = 0; kc < 8; ++kc) {
        const int k = kc*8 + tig;
        qf[kc][0] = __float_as_uint(sm.stage[wrow+gid  ][k  ]);
        qf[kc][1] = __float_as_uint(sm.stage[wrow+gid+8][k  ]);
        qf[kc][2] = __float_as_uint(sm.stage[wrow+gid  ][k+4]);
        qf[kc][3] = __float_as_uint(sm.stage[wrow+gid+8][k+4]);
    }
    __syncthreads();  // stage free for P reuse

    float oacc[8][4];
    #pragma unroll
    for (int nt = 0; nt < 8; ++nt)
        #pragma unroll
        for (int i = 0; i < 4; ++i) oacc[nt][i] = 0.f;
    float m0v = -1e30f, m1v = -1e30f, l0 = 0.f, l1 = 0.f;

    for (int j = 0; j < SS/FK; ++j) {
        // ---- stage K [key][d] and V^T [d][key]
        #pragma unroll
        for (int i = 0; i < 4; ++i) {
            const int idx = tid + i*256;
            const int r = idx >> 4, c = (idx & 15) << 2;
            float4 kv = *(const float4*)(Kz + (ll)(j*FK + r)*DD + c);
            kv.x = ftf32(kv.x); kv.y = ftf32(kv.y); kv.z = ftf32(kv.z); kv.w = ftf32(kv.w);
            *(float4*)&sm.ks[r][c] = kv;
            float4 vv = *(const float4*)(Vz + (ll)(j*FK + r)*DD + c);
            vv.x = ftf32(vv.x); vv.y = ftf32(vv.y); vv.z = ftf32(vv.z); vv.w = ftf32(vv.w);
            sm.vs[c+0][r] = vv.x; sm.vs[c+1][r] = vv.y;
            sm.vs[c+2][r] = vv.z; sm.vs[c+3][r] = vv.w;
        }
        __syncthreads();

        // ---- S = Q @ K^T
        float sacc[8][4];
        #pragma unroll
        for (int nt = 0; nt < 8; ++nt)
            #pragma unroll
            for (int i = 0; i < 4; ++i) sacc[nt][i] = 0.f;
        #pragma unroll
        for (int kc = 0; kc < 8; ++kc) {
            const int k = kc*8 + tig;
            #pragma unroll
            for (int nt = 0; nt < 8; ++nt) {
                const int cc = nt*8 + gid;
                uint32_t bf[2];
                bf[0] = __float_as_uint(sm.ks[cc][k  ]);
                bf[1] = __float_as_uint(sm.ks[cc][k+4]);
                mma_tf32(sacc[nt], qf[kc], bf);
            }
        }

        // ---- + bias, row max
        float mx0 = -1e30f, mx1 = -1e30f;
        const float* br0 = Bz + (ll)(wrow+gid  )*SS + j*FK + 2*tig;
        const float* br1 = Bz + (ll)(wrow+gid+8)*SS + j*FK + 2*tig;
        #pragma unroll
        for (int nt = 0; nt < 8; ++nt) {
            const float2 b0 = *(const float2*)(br0 + nt*8);
            const float2 b1 = *(const float2*)(br1 + nt*8);
            sacc[nt][0] += b0.x; sacc[nt][1] += b0.y;
            sacc[nt][2] += b1.x; sacc[nt][3] += b1.y;
            mx0 = fmaxf(mx0, fmaxf(sacc[nt][0], sacc[nt][1]));
            mx1 = fmaxf(mx1, fmaxf(sacc[nt][2], sacc[nt][3]));
        }
        #pragma unroll
        for (int o = 1; o <= 2; o <<= 1) {
            mx0 = fmaxf(mx0, __shfl_xor_sync(0xFFFFFFFFu, mx0, o));
            mx1 = fmaxf(mx1, __shfl_xor_sync(0xFFFFFFFFu, mx1, o));
        }
        const float mn0 = fmaxf(m0v, mx0), mn1 = fmaxf(m1v, mx1);
        const float sc0 = __expf(m0v - mn0), sc1 = __expf(m1v - mn1);
        m0v = mn0; m1v = mn1;

        // ---- P = exp(S - m), stage to smem (tf32), accumulate row sums
        float rs0 = 0.f, rs1 = 0.f;
        #pragma unroll
        for (int nt = 0; nt < 8; ++nt) {
            const float p0 = __expf(sacc[nt][0] - mn0);
            const float p1 = __expf(sacc[nt][1] - mn0);
            const float p2 = __expf(sacc[nt][2] - mn1);
            const float p3 = __expf(sacc[nt][3] - mn1);
            rs0 += p0 + p1; rs1 += p2 + p3;
            float2 w0; w0.x = ftf32(p0); w0.y = ftf32(p1);
            float2 w1; w1.x = ftf32(p2); w1.y = ftf32(p3);
            *(float2*)&sm.stage[wrow+gid  ][nt*8 + 2*tig] = w0;
            *(float2*)&sm.stage[wrow+gid+8][nt*8 + 2*tig] = w1;
        }
        #pragma unroll
        for (int o = 1; o <= 2; o <<= 1) {
            rs0 += __shfl_xor_sync(0xFFFFFFFFu, rs0, o);
            rs1 += __shfl_xor_sync(0xFFFFFFFFu, rs1, o);
        }
        l0 = l0*sc0 + rs0;
        l1 = l1*sc1 + rs1;
        #pragma unroll
        for (int nt = 0; nt < 8; ++nt) {
            oacc[nt][0] *= sc0; oacc[nt][1] *= sc0;
            oacc[nt][2] *= sc1; oacc[nt][3] *= sc1;
        }
        __syncwarp();   // P tile is warp-local

        // ---- O += P @ V
        #pragma unroll
        for (int kc = 0; kc < 8; ++kc) {
            const int k = kc*8 + tig;
            uint32_t af[4];
            af[0] = __float_as_uint(sm.stage[wrow+gid  ][k  ]);
            af[1] = __float_as_uint(sm.stage[wrow+gid+8][k  ]);
            af[2] = __float_as_uint(sm.stage[wrow+gid  ][k+4]);
            af[3] = __float_as_uint(sm.stage[wrow+gid+8][k+4]);
            #pragma unroll
            for (int nt = 0; nt < 8; ++nt) {
                const int cc = nt*8 + gid;
                uint32_t bf[2];
                bf[0] = __float_as_uint(sm.vs[cc][k  ]);
                bf[1] = __float_as_uint(sm.vs[cc][k+4]);
                mma_tf32(oacc[nt], af, bf);
            }
        }
        __syncthreads();  // all warps done with ks/vs before next stage
    }

    // ---- finalize: O /= l, write ctx [B,S,D]
    const float inv0 = 1.f / l0, inv1 = 1.f / l1;
    #pragma unroll
    for (int nt = 0; nt < 8; ++nt) {
        const int col = nt*8 + 2*tig;
        float2 w0; w0.x = oacc[nt][0]*inv0; w0.y = oacc[nt][1]*inv0;
        float2 w1; w1.x = oacc[nt][2]*inv1; w1.y = oacc[nt][3]*inv1;
        *(float2*)(Cz + (ll)(q0 + wrow + gid    )*DD + col) = w0;
        *(float2*)(Cz + (ll)(q0 + wrow + gid + 8)*DD + col) = w1;
    }
}

// ---------------- host orchestration ----------------------------------------
extern "C" void kernel_launch(void* const* d_in, const int* in_sizes, int n_in,
                              void* d_out, int out_size)
{
    const float* Wk   = (const float*)d_in[0]; // primals_1
    const float* Wo   = (const float*)d_in[1]; // primals_2
    const float* Wq   = (const float*)d_in[2]; // primals_3
    const float* Wv   = (const float*)d_in[3]; // primals_4
    const float* G1   = (const float*)d_in[4]; // primals_5
    const float* Wi   = (const float*)d_in[5]; // primals_6 [DFF,D]
    const float* Wo2  = (const float*)d_in[6]; // primals_7 [D,DFF]
    const float* G2   = (const float*)d_in[7]; // primals_8
    const float* X    = (const float*)d_in[8]; // primals_9 [B,S,D]
    const float* Bias = (const float*)d_in[9]; // primals_10 [B,H,S,S]
    float* Out = (float*)d_out;

    float *h, *q, *k, *v, *ctx, *y, *h2, *ff;
    cudaGetSymbolAddress((void**)&h,   g_h);
    cudaGetSymbolAddress((void**)&q,   g_q);
    cudaGetSymbolAddress((void**)&k,   g_k);
    cudaGetSymbolAddress((void**)&v,   g_v);
    cudaGetSymbolAddress((void**)&ctx, g_ctx);
    cudaGetSymbolAddress((void**)&y,   g_y);
    cudaGetSymbolAddress((void**)&h2,  g_h2);
    cudaGetSymbolAddress((void**)&ff,  g_ff);

    const dim3 blk(256);
    const int flash_smem = (int)sizeof(FlashS);
    cudaFuncSetAttribute(flash_attn, cudaFuncAttributeMaxDynamicSharedMemorySize, flash_smem);

    // 1) h = rmsnorm(x, G1)
    rmsnorm_kernel<<<MTOK, 128>>>(X, G1, h);

    // 2) q/k/v = h @ W^T  (NT, M=8192 N=512 K=512)
    gemm_tc<0,128,true><<<dim3(4,64,1), blk>>>(h, Wq, nullptr, q, MTOK, DD, DD,
        DD, DD, 0, DD, 1, 0,0, 0,0, 0,0, 0,0);
    gemm_tc<0,128,true><<<dim3(4,64,1), blk>>>(h, Wk, nullptr, k, MTOK, DD, DD,
        DD, DD, 0, DD, 1, 0,0, 0,0, 0,0, 0,0);
    gemm_tc<0,128,true><<<dim3(4,64,1), blk>>>(h, Wv, nullptr, v, MTOK, DD, DD,
        DD, DD, 0, DD, 1, 0,0, 0,0, 0,0, 0,0);

    // 3-5) fused attention: ctx = softmax(QK^T + bias) @ V  -> [B,S,D]
    flash_attn<<<dim3(SS/FQ, BB*HH), blk, flash_smem>>>(q, k, v, Bias, ctx);

    // 6) y = x + ctx @ Wo^T
    gemm_tc<2,128,true><<<dim3(4,64,1), blk>>>(ctx, Wo, X, y, MTOK, DD, DD,
        DD, DD, DD, DD, 1, 0,0, 0,0, 0,0, 0,0);

    // 7) h2 = rmsnorm(y, G2)
    rmsnorm_kernel<<<MTOK, 128>>>(y, G2, h2);

    // 8) ff = relu(h2 @ Wi^T)   (M=8192 N=2048 K=512)
    gemm_tc<1,128,true><<<dim3(16,64,1), blk>>>(h2, Wi, nullptr, ff, MTOK, DFF, DD,
        DD, DD, 0, DFF, 1, 0,0, 0,0, 0,0, 0,0);

    // 9) out = y + ff @ Wo2^T   (M=8192 N=512 K=2048)
    gemm_tc<2,128,true><<<dim3(4,64,1), blk>>>(ff, Wo2, y, Out, MTOK, DD, DFF,
        DFF, DFF, DD, DD, 1, 0,0, 0,0, 0,0, 0,0);
}

// round 5
// speedup vs baseline: 2.7539x; 1.1586x over previous
#include <cuda_runtime.h>
#include <cstdint>

// Shapes (compile-time constants)
#define BB 8
#define SS 1024
#define DD 512
#define HH 8
#define HD 64
#define DFF 2048
#define MTOK (BB*SS)   // 8192

typedef long long ll;

// ---------------- scratch (device globals: allocation-guard safe) -----------
__device__ float g_h  [MTOK*DD];        // rmsnorm1 output
__device__ float g_q  [MTOK*DD];
__device__ float g_k  [MTOK*DD];
__device__ float g_v  [MTOK*DD];
__device__ float g_ctx[MTOK*DD];
__device__ float g_y  [MTOK*DD];        // residual after attention
__device__ float g_h2 [MTOK*DD];        // rmsnorm2 output
__device__ float g_ff [MTOK*DFF];       // relu(ffn1)

// ---------------- helpers ----------------------------------------------------
__device__ __forceinline__ uint32_t smem_u32(const void* p) {
    uint32_t a;
    asm("{ .reg .u64 t; cvta.to.shared.u64 t, %1; cvt.u32.u64 %0, t; }"
        : "=r"(a) : "l"(p));
    return a;
}
__device__ __forceinline__ float ftf32(float x) {
    uint32_t o, i = __float_as_uint(x);
    asm("cvt.rna.tf32.f32 %0, %1;" : "=r"(o) : "r"(i));
    return __uint_as_float(o);
}
__device__ __forceinline__ void mma_tf32(float c[4], const uint32_t a[4], const uint32_t b[2]) {
    asm volatile(
        "mma.sync.aligned.m16n8k8.row.col.f32.tf32.tf32.f32 "
        "{%0,%1,%2,%3}, {%4,%5,%6,%7}, {%8,%9}, {%0,%1,%2,%3};\n"
        : "+f"(c[0]), "+f"(c[1]), "+f"(c[2]), "+f"(c[3])
        : "r"(a[0]), "r"(a[1]), "r"(a[2]), "r"(a[3]), "r"(b[0]), "r"(b[1]));
}

#define CP_ASYNC16(dst, src) \
    asm volatile("cp.async.cg.shared.global [%0], [%1], 16;\n" :: "r"(dst), "l"(src))
#define CP_COMMIT() asm volatile("cp.async.commit_group;\n" ::: "memory")
#define CP_WAIT(n)  asm volatile("cp.async.wait_group %0;\n" :: "n"(n) : "memory")

// ---------------- RMSNorm: one block (128 thr) per row of 512 ----------------
__global__ __launch_bounds__(128) void rmsnorm_kernel(
    const float* __restrict__ x, const float* __restrict__ w,
    float* __restrict__ out)
{
    const int row = blockIdx.x;
    const int t = threadIdx.x;
    const float4 v = ((const float4*)(x + (ll)row*DD))[t];
    float ss = v.x*v.x + v.y*v.y + v.z*v.z + v.w*v.w;
    #pragma unroll
    for (int o = 16; o; o >>= 1) ss += __shfl_xor_sync(0xFFFFFFFFu, ss, o);
    __shared__ float wsum[4];
    if ((t & 31) == 0) wsum[t >> 5] = ss;
    __syncthreads();
    const float tot = wsum[0] + wsum[1] + wsum[2] + wsum[3];
    const float r = rsqrtf(tot * (1.0f/DD) + 1e-6f);
    const float4 wv = ((const float4*)w)[t];
    float4 o4;
    o4.x = v.x * r * wv.x; o4.y = v.y * r * wv.y;
    o4.z = v.z * r * wv.z; o4.w = v.w * r * wv.w;
    ((float4*)(out + (ll)row*DD))[t] = o4;
}

// ---------------- TF32 mma.sync GEMM, 64x64 warp tiles -----------------------
// C[m,n] = sum_k A[m,k]*B[n,k]  (both K-major / NT).
// 128x128 block, 128 threads (4 warps, 2x2), warp tile 64x64, BK=16,
// 3-stage cp.async pipeline, raw-f32 operands (HW tf32 truncation).
// EPI: 0=none, 1=relu, 2=+Add.  NMAT=3: fused QKV (B/C selected by blockIdx.z).
#define STG   3
#define PAD   20                    // floats per smem row (16 + 4)
#define ATILF (128*PAD)             // 2560 floats = 10240 B per operand tile
#define STGF  (2*ATILF)             // floats per stage
#define GSMEM (STG*STGF*4)          // 61440 B

template<int EPI, int NMAT>
__global__ __launch_bounds__(128, 2) void gemm_tc2(
    const float* __restrict__ A,
    const float* __restrict__ B0, const float* __restrict__ B1,
    const float* __restrict__ B2,
    const float* __restrict__ Add,
    float* __restrict__ C0, float* __restrict__ C1, float* __restrict__ C2,
    int K, int N)
{
    extern __shared__ float dsm[];

    const float* B = B0;
    float*       C = C0;
    if (NMAT == 3) {
        if (blockIdx.z == 1) { B = B1; C = C1; }
        else if (blockIdx.z == 2) { B = B2; C = C2; }
    }

    const int tid  = threadIdx.x;
    const int warp = tid >> 5, lane = tid & 31;
    const int wm   = warp >> 1, wn = warp & 1;      // 2x2 warp grid
    const int gid  = lane >> 2, tig = lane & 3;
    const int m0   = blockIdx.y * 128;
    const int n0   = blockIdx.x * 128;

    const uint32_t smb = smem_u32(dsm);
    const float* Ab = A + (ll)m0 * K;
    const float* Bb = B + (ll)n0 * K;

    float acc[4][8][4];
    #pragma unroll
    for (int mt = 0; mt < 4; ++mt)
        #pragma unroll
        for (int nt = 0; nt < 8; ++nt)
            #pragma unroll
            for (int i = 0; i < 4; ++i) acc[mt][nt][i] = 0.f;

    // stage j -> buffer j%STG. Each thread copies 4x16B of A and of B.
    auto issue = [&](int j) {
        const int st = j % STG;
        const int k0 = j * 16;
        const uint32_t ab = smb + st*STGF*4;
        const uint32_t bb = ab + ATILF*4;
        #pragma unroll
        for (int i = 0; i < 4; ++i) {
            const int id = tid + i*128;
            const int r = id >> 2, c = id & 3;
            CP_ASYNC16(ab + (r*PAD + c*4)*4, Ab + (ll)r*K + k0 + c*4);
            CP_ASYNC16(bb + (r*PAD + c*4)*4, Bb + (ll)r*K + k0 + c*4);
        }
        CP_COMMIT();
    };

    const int NC = K / 16;          // >= 32 for all our GEMMs
    issue(0); issue(1); issue(2);

    for (int j = 0; j < NC; ++j) {
        CP_WAIT(STG-1);
        __syncthreads();

        const int stF = (j % STG)*STGF;
        const float* As = dsm + stF;
        const float* Bs = dsm + stF + ATILF;

        #pragma unroll
        for (int ks = 0; ks < 2; ++ks) {
            const int k = ks*8 + tig;
            uint32_t af[4][4], bf[8][2];
            #pragma unroll
            for (int mt = 0; mt < 4; ++mt) {
                const int r = (wm*64 + mt*16 + gid)*PAD + k;
                af[mt][0] = __float_as_uint(As[r]);
                af[mt][1] = __float_as_uint(As[r + 8*PAD]);
                af[mt][2] = __float_as_uint(As[r + 4]);
                af[mt][3] = __float_as_uint(As[r + 8*PAD + 4]);
            }
            #pragma unroll
            for (int nt = 0; nt < 8; ++nt) {
                const int r = (wn*64 + nt*8 + gid)*PAD + k;
                bf[nt][0] = __float_as_uint(Bs[r]);
                bf[nt][1] = __float_as_uint(Bs[r + 4]);
            }
            #pragma unroll
            for (int mt = 0; mt < 4; ++mt)
                #pragma unroll
                for (int nt = 0; nt < 8; ++nt)
                    mma_tf32(acc[mt][nt], af[mt], bf[nt]);
        }

        __syncthreads();
        if (j + STG < NC) issue(j + STG);
    }

    // ---- epilogue
    #pragma unroll
    for (int mt = 0; mt < 4; ++mt) {
        #pragma unroll
        for (int nt = 0; nt < 8; ++nt) {
            const int col = n0 + wn*64 + nt*8 + tig*2;
            #pragma unroll
            for (int h = 0; h < 2; ++h) {
                const ll row = (ll)(m0 + wm*64 + mt*16 + gid + h*8);
                float2 v;
                v.x = acc[mt][nt][h*2+0];
                v.y = acc[mt][nt][h*2+1];
                if (EPI == 1) { v.x = fmaxf(v.x, 0.f); v.y = fmaxf(v.y, 0.f); }
                if (EPI == 2) {
                    const float2 ad = *(const float2*)(Add + row*N + col);
                    v.x += ad.x; v.y += ad.y;
                }
                *(float2*)(C + row*N + col) = v;
            }
        }
    }
}

// ---------------- Fused flash attention (unchanged, passing) -----------------
#define FQ 128
#define FK 64
#define FLDS 68   // 64 + 4 pad

struct FlashS {
    float stage[FQ][FLDS];
    float ks[FK][FLDS];
    float vs[HD][FLDS];
};

__global__ __launch_bounds__(256) void flash_attn(
    const float* __restrict__ Q, const float* __restrict__ Kg,
    const float* __restrict__ Vg, const float* __restrict__ Bias,
    float* __restrict__ Ctx)
{
    extern __shared__ char smraw[];
    FlashS& sm = *reinterpret_cast<FlashS*>(smraw);

    const int z  = blockIdx.y;
    const int b  = z >> 3, hh = z & 7;
    const int q0 = blockIdx.x * FQ;
    const ll off = (ll)b*SS*DD + (ll)hh*HD;
    const float* Qz = Q  + off;
    const float* Kz = Kg + off;
    const float* Vz = Vg + off;
    const float* Bz = Bias + ((ll)z*SS + q0)*SS;
    float*       Cz = Ctx + off;

    const int tid = threadIdx.x, warp = tid >> 5, lane = tid & 31;
    const int gid = lane >> 2, tig = lane & 3;
    const int wrow = warp * 16;

    #pragma unroll
    for (int i = 0; i < 8; ++i) {
        const int idx = tid + i*256;
        const int r = idx >> 4, c = (idx & 15) << 2;
        float4 v = *(const float4*)(Qz + (ll)(q0 + r)*DD + c);
        v.x = ftf32(v.x); v.y = ftf32(v.y); v.z = ftf32(v.z); v.w = ftf32(v.w);
        *(float4*)&sm.stage[r][c] = v;
    }
    __syncthreads();
    uint32_t qf[8][4];
    #pragma unroll
    for (int kc = 0; kc < 8; ++kc) {
        const int k = kc*8 + tig;
        qf[kc][0] = __float_as_uint(sm.stage[wrow+gid  ][k  ]);
        qf[kc][1] = __float_as_uint(sm.stage[wrow+gid+8][k  ]);
        qf[kc][2] = __float_as_uint(sm.stage[wrow+gid  ][k+4]);
        qf[kc][3] = __float_as_uint(sm.stage[wrow+gid+8][k+4]);
    }
    __syncthreads();

    float oacc[8][4];
    #pragma unroll
    for (int nt = 0; nt < 8; ++nt)
        #pragma unroll
        for (int i = 0; i < 4; ++i) oacc[nt][i] = 0.f;
    float m0v = -1e30f, m1v = -1e30f, l0 = 0.f, l1 = 0.f;

    for (int j = 0; j < SS/FK; ++j) {
        #pragma unroll
        for (int i = 0; i < 4; ++i) {
            const int idx = tid + i*256;
            const int r = idx >> 4, c = (idx & 15) << 2;
            float4 kv = *(const float4*)(Kz + (ll)(j*FK + r)*DD + c);
            kv.x = ftf32(kv.x); kv.y = ftf32(kv.y); kv.z = ftf32(kv.z); kv.w = ftf32(kv.w);
            *(float4*)&sm.ks[r][c] = kv;
            float4 vv = *(const float4*)(Vz + (ll)(j*FK + r)*DD + c);
            vv.x = ftf32(vv.x); vv.y = ftf32(vv.y); vv.z = ftf32(vv.z); vv.w = ftf32(vv.w);
            sm.vs[c+0][r] = vv.x; sm.vs[c+1][r] = vv.y;
            sm.vs[c+2][r] = vv.z; sm.vs[c+3][r] = vv.w;
        }
        __syncthreads();

        float sacc[8][4];
        #pragma unroll
        for (int nt = 0; nt < 8; ++nt)
            #pragma unroll
            for (int i = 0; i < 4; ++i) sacc[nt][i] = 0.f;
        #pragma unroll
        for (int kc = 0; kc < 8; ++kc) {
            const int k = kc*8 + tig;
            #pragma unroll
            for (int nt = 0; nt < 8; ++nt) {
                const int cc = nt*8 + gid;
                uint32_t bf[2];
                bf[0] = __float_as_uint(sm.ks[cc][k  ]);
                bf[1] = __float_as_uint(sm.ks[cc][k+4]);
                mma_tf32(sacc[nt], qf[kc], bf);
            }
        }

        float mx0 = -1e30f, mx1 = -1e30f;
        const float* br0 = Bz + (ll)(wrow+gid  )*SS + j*FK + 2*tig;
        const float* br1 = Bz + (ll)(wrow+gid+8)*SS + j*FK + 2*tig;
        #pragma unroll
        for (int nt = 0; nt < 8; ++nt) {
            const float2 b0 = *(const float2*)(br0 + nt*8);
            const float2 b1 = *(const float2*)(br1 + nt*8);
            sacc[nt][0] += b0.x; sacc[nt][1] += b0.y;
            sacc[nt][2] += b1.x; sacc[nt][3] += b1.y;
            mx0 = fmaxf(mx0, fmaxf(sacc[nt][0], sacc[nt][1]));
            mx1 = fmaxf(mx1, fmaxf(sacc[nt][2], sacc[nt][3]));
        }
        #pragma unroll
        for (int o = 1; o <= 2; o <<= 1) {
            mx0 = fmaxf(mx0, __shfl_xor_sync(0xFFFFFFFFu, mx0, o));
            mx1 = fmaxf(mx1, __shfl_xor_sync(0xFFFFFFFFu, mx1, o));
        }
        const float mn0 = fmaxf(m0v, mx0), mn1 = fmaxf(m1v, mx1);
        const float sc0 = __expf(m0v - mn0), sc1 = __expf(m1v - mn1);
        m0v = mn0; m1v = mn1;

        float rs0 = 0.f, rs1 = 0.f;
        #pragma unroll
        for (int nt = 0; nt < 8; ++nt) {
            const float p0 = __expf(sacc[nt][0] - mn0);
            const float p1 = __expf(sacc[nt][1] - mn0);
            const float p2 = __expf(sacc[nt][2] - mn1);
            const float p3 = __expf(sacc[nt][3] - mn1);
            rs0 += p0 + p1; rs1 += p2 + p3;
            float2 w0; w0.x = ftf32(p0); w0.y = ftf32(p1);
            float2 w1; w1.x = ftf32(p2); w1.y = ftf32(p3);
            *(float2*)&sm.stage[wrow+gid  ][nt*8 + 2*tig] = w0;
            *(float2*)&sm.stage[wrow+gid+8][nt*8 + 2*tig] = w1;
        }
        #pragma unroll
        for (int o = 1; o <= 2; o <<= 1) {
            rs0 += __shfl_xor_sync(0xFFFFFFFFu, rs0, o);
            rs1 += __shfl_xor_sync(0xFFFFFFFFu, rs1, o);
        }
        l0 = l0*sc0 + rs0;
        l1 = l1*sc1 + rs1;
        #pragma unroll
        for (int nt = 0; nt < 8; ++nt) {
            oacc[nt][0] *= sc0; oacc[nt][1] *= sc0;
            oacc[nt][2] *= sc1; oacc[nt][3] *= sc1;
        }
        __syncwarp();

        #pragma unroll
        for (int kc = 0; kc < 8; ++kc) {
            const int k = kc*8 + tig;
            uint32_t af[4];
            af[0] = __float_as_uint(sm.stage[wrow+gid  ][k  ]);
            af[1] = __float_as_uint(sm.stage[wrow+gid+8][k  ]);
            af[2] = __float_as_uint(sm.stage[wrow+gid  ][k+4]);
            af[3] = __float_as_uint(sm.stage[wrow+gid+8][k+4]);
            #pragma unroll
            for (int nt = 0; nt < 8; ++nt) {
                const int cc = nt*8 + gid;
                uint32_t bf[2];
                bf[0] = __float_as_uint(sm.vs[cc][k  ]);
                bf[1] = __float_as_uint(sm.vs[cc][k+4]);
                mma_tf32(oacc[nt], af, bf);
            }
        }
        __syncthreads();
    }

    const float inv0 = 1.f / l0, inv1 = 1.f / l1;
    #pragma unroll
    for (int nt = 0; nt < 8; ++nt) {
        const int col = nt*8 + 2*tig;
        float2 w0; w0.x = oacc[nt][0]*inv0; w0.y = oacc[nt][1]*inv0;
        float2 w1; w1.x = oacc[nt][2]*inv1; w1.y = oacc[nt][3]*inv1;
        *(float2*)(Cz + (ll)(q0 + wrow + gid    )*DD + col) = w0;
        *(float2*)(Cz + (ll)(q0 + wrow + gid + 8)*DD + col) = w1;
    }
}

// ---------------- host orchestration -----------------------------------------
extern "C" void kernel_launch(void* const* d_in, const int* in_sizes, int n_in,
                              void* d_out, int out_size)
{
    const float* Wk   = (const float*)d_in[0]; // primals_1
    const float* Wo   = (const float*)d_in[1]; // primals_2
    const float* Wq   = (const float*)d_in[2]; // primals_3
    const float* Wv   = (const float*)d_in[3]; // primals_4
    const float* G1   = (const float*)d_in[4]; // primals_5
    const float* Wi   = (const float*)d_in[5]; // primals_6 [DFF,D]
    const float* Wo2  = (const float*)d_in[6]; // primals_7 [D,DFF]
    const float* G2   = (const float*)d_in[7]; // primals_8
    const float* X    = (const float*)d_in[8]; // primals_9 [B,S,D]
    const float* Bias = (const float*)d_in[9]; // primals_10 [B,H,S,S]
    float* Out = (float*)d_out;

    float *h, *q, *k, *v, *ctx, *y, *h2, *ff;
    cudaGetSymbolAddress((void**)&h,   g_h);
    cudaGetSymbolAddress((void**)&q,   g_q);
    cudaGetSymbolAddress((void**)&k,   g_k);
    cudaGetSymbolAddress((void**)&v,   g_v);
    cudaGetSymbolAddress((void**)&ctx, g_ctx);
    cudaGetSymbolAddress((void**)&y,   g_y);
    cudaGetSymbolAddress((void**)&h2,  g_h2);
    cudaGetSymbolAddress((void**)&ff,  g_ff);

    const int flash_smem = (int)sizeof(FlashS);
    cudaFuncSetAttribute(flash_attn, cudaFuncAttributeMaxDynamicSharedMemorySize, flash_smem);
    cudaFuncSetAttribute(gemm_tc2<0,3>, cudaFuncAttributeMaxDynamicSharedMemorySize, GSMEM);
    cudaFuncSetAttribute(gemm_tc2<1,1>, cudaFuncAttributeMaxDynamicSharedMemorySize, GSMEM);
    cudaFuncSetAttribute(gemm_tc2<2,1>, cudaFuncAttributeMaxDynamicSharedMemorySize, GSMEM);

    // 1) h = rmsnorm(x, G1)
    rmsnorm_kernel<<<MTOK, 128>>>(X, G1, h);

    // 2) fused q/k/v = h @ W{q,k,v}^T  (NT, M=8192 N=512 K=512, z selects W)
    gemm_tc2<0,3><<<dim3(4,64,3), 128, GSMEM>>>(h, Wq, Wk, Wv, nullptr,
                                                q, k, v, DD, DD);

    // 3-5) fused attention: ctx = softmax(QK^T + bias) @ V  -> [B,S,D]
    flash_attn<<<dim3(SS/FQ, BB*HH), 256, flash_smem>>>(q, k, v, Bias, ctx);

    // 6) y = x + ctx @ Wo^T
    gemm_tc2<2,1><<<dim3(4,64), 128, GSMEM>>>(ctx, Wo, nullptr, nullptr, X,
                                              y, nullptr, nullptr, DD, DD);

    // 7) h2 = rmsnorm(y, G2)
    rmsnorm_kernel<<<MTOK, 128>>>(y, G2, h2);

    // 8) ff = relu(h2 @ Wi^T)   (M=8192 N=2048 K=512)
    gemm_tc2<1,1><<<dim3(16,64), 128, GSMEM>>>(h2, Wi, nullptr, nullptr, nullptr,
                                               ff, nullptr, nullptr, DD, DFF);

    // 9) out = y + ff @ Wo2^T   (M=8192 N=512 K=2048)
    gemm_tc2<2,1><<<dim3(4,64), 128, GSMEM>>>(ff, Wo2, nullptr, nullptr, y,
                                              Out, nullptr, nullptr, DFF, DD);
}